// round 17
// baseline (speedup 1.0000x reference)
#include <cuda_runtime.h>
#include <cuda_fp16.h>
#include <math.h>

#define NUM_B 2
#define NUM_C 256
#define NUM_H 256
#define NUM_W 256
#define NUM_N 512
#define OUT_H 7
#define OUT_W 7
#define NBIN 49
#define HW (NUM_H * NUM_W)
#define CHW (NUM_C * HW)
#define C_HALF 128
#define SOUT_PAD 133
#define T_PER_BATCH 4096          // 8 x 8 x 64 transpose tiles per batch
#define P_PER_BATCH (NUM_N * 2)   // 1024 pool blocks per batch

// fp16 NHWC copy of x: xT[b][y][x][c]  (64 MB total)
__device__ __half xT_buf[(size_t)NUM_B * NUM_H * NUM_W * NUM_C];

struct PoolSmem {
    int   pos[NBIN][4];
    float wgt[NBIN][4];
    float sout[NBIN][SOUT_PAD];
};
// transpose needs 4*32*33*4 = 16896 B < sizeof(PoolSmem) = 27636 B

// ---------------------------------------------------------------------------
// Transpose one (c0,w0) 32x32 tile over 4 h-slices (R13 layout). 256 threads.
// t in [0, 4096): w0=(t&7)*32, c0=((t>>3)&7)*32, h0=(t>>6)*4.
// ---------------------------------------------------------------------------
__device__ __forceinline__ void transpose_tile(const float* __restrict__ x,
                                               int b, int t, int tid,
                                               char* smemraw)
{
    float (*tile)[32][33] = reinterpret_cast<float (*)[32][33]>(smemraw);

    const int w0 = (t & 7) * 32;
    const int c0 = ((t >> 3) & 7) * 32;
    const int h0 = (t >> 6) * 4;
    const int tx = tid & 7;      // 0..7  (float4 index)
    const int ty = tid >> 3;     // 0..31

    const float* src = x + (((size_t)b * NUM_C + c0 + ty) * NUM_H + h0) * NUM_W
                         + w0 + tx * 4;
    float4 v[4];
    #pragma unroll
    for (int k = 0; k < 4; ++k)
        v[k] = *reinterpret_cast<const float4*>(src + (size_t)k * NUM_W);

    #pragma unroll
    for (int k = 0; k < 4; ++k) {
        tile[k][ty][tx * 4 + 0] = v[k].x;
        tile[k][ty][tx * 4 + 1] = v[k].y;
        tile[k][ty][tx * 4 + 2] = v[k].z;
        tile[k][ty][tx * 4 + 3] = v[k].w;
    }
    __syncthreads();

    #pragma unroll
    for (int k = 0; k < 4; ++k) {
        __half2 lo = __floats2half2_rn(tile[k][tx * 4 + 0][ty], tile[k][tx * 4 + 1][ty]);
        __half2 hi = __floats2half2_rn(tile[k][tx * 4 + 2][ty], tile[k][tx * 4 + 3][ty]);
        uint2 pak;
        pak.x = *reinterpret_cast<unsigned int*>(&lo);
        pak.y = *reinterpret_cast<unsigned int*>(&hi);

        __half* dst = xT_buf + (((size_t)b * NUM_H + h0 + k) * NUM_W + w0 + ty) * NUM_C
                             + c0 + tx * 4;
        *reinterpret_cast<uint2*>(dst) = pak;
    }
}

// ---------------------------------------------------------------------------
// Pool one (roi, half) pair from fp16 NHWC (R13 version). 256 threads.
// ---------------------------------------------------------------------------
__device__ __forceinline__ void pool_block(const float* __restrict__ boxes,
                                           float* __restrict__ out,
                                           int b, int p, int tid,
                                           char* smemraw)
{
    PoolSmem* sm = reinterpret_cast<PoolSmem*>(smemraw);

    const int roi  = b * NUM_N + (p >> 1);
    const int half = p & 1;

    if (tid < NBIN) {
        const float* bx = boxes + roi * 5;
        float cx  = __fmul_rn(bx[0], 0.25f);
        float cy  = __fmul_rn(bx[1], 0.25f);
        float w   = __fmul_rn(bx[2], 0.25f);
        float h   = __fmul_rn(bx[3], 0.25f);
        float ang = __fmul_rn(bx[4], 0.017453292519943295f);

        float Sx = __fdiv_rn(w, 7.0f);
        float Sy = __fdiv_rn(h, 7.0f);
        float ca = cosf(ang);
        float sa = sinf(ang);

        const float dxc = -3.5f;
        const float dyc = -3.5f;

        float M00 = __fmul_rn(ca, Sx);
        float M01 = __fmul_rn(sa, Sy);
        float M02 = __fadd_rn(__fadd_rn(__fmul_rn(__fmul_rn(ca, Sx), dxc),
                                        __fmul_rn(__fmul_rn(sa, Sy), dyc)), cx);
        float M10 = __fmul_rn(-sa, Sx);
        float M11 = __fmul_rn(ca, Sy);
        float M12 = __fadd_rn(__fadd_rn(__fmul_rn(__fmul_rn(-sa, Sx), dxc),
                                        __fmul_rn(__fmul_rn(ca, Sy), dyc)), cy);

        int ph = tid / OUT_W;
        int pw = tid - ph * OUT_W;

        const float offx[4] = {0.f, 0.f, 1.f, 1.f};
        const float offy[4] = {0.f, 1.f, 0.f, 1.f};

        float minX =  3.0e38f, maxX = -3.0e38f;
        float minY =  3.0e38f, maxY = -3.0e38f;
        #pragma unroll
        for (int k = 0; k < 4; ++k) {
            float pwc = (float)pw + offx[k];
            float phc = (float)ph + offy[k];
            float X = __fadd_rn(__fadd_rn(__fmul_rn(M00, pwc), __fmul_rn(M01, phc)), M02);
            float Y = __fadd_rn(__fadd_rn(__fmul_rn(M10, pwc), __fmul_rn(M11, phc)), M12);
            minX = fminf(minX, X); maxX = fmaxf(maxX, X);
            minY = fminf(minY, Y); maxY = fmaxf(maxY, Y);
        }

        float lM = fmaxf(rintf(minX), 0.0f);
        float rM = fminf(rintf(maxX), (float)(NUM_W - 1));
        float tM = fmaxf(rintf(minY), 0.0f);
        float bM = fminf(rintf(maxY), (float)(NUM_H - 1));

        float bcx = __fmul_rn(__fadd_rn(lM, rM), 0.5f);
        float bcy = __fmul_rn(__fadd_rn(tM, bM), 0.5f);

        float flx = floorf(bcx);
        float fly = floorf(bcy);
        int il = (int)flx;
        int it = (int)fly;
        int ir = (int)ceilf(bcx);
        int ib = (int)ceilf(bcy);
        float rx = __fsub_rn(bcx, flx);
        float ry = __fsub_rn(bcy, fly);

        float omrx = __fsub_rn(1.0f, rx);
        float omry = __fsub_rn(1.0f, ry);
        float wlt = __fmul_rn(omrx, omry);
        float wrt = __fmul_rn(rx,   omry);
        float wrb = __fmul_rn(rx,   ry);
        float wlb = __fmul_rn(omrx, ry);

        bool vl = (il >= 0) && (il < NUM_W);
        bool vr = (ir >= 0) && (ir < NUM_W);
        bool vt = (it >= 0) && (it < NUM_H);
        bool vb = (ib >= 0) && (ib < NUM_H);

        int cl = min(max(il, 0), NUM_W - 1);
        int cr = min(max(ir, 0), NUM_W - 1);
        int ct = min(max(it, 0), NUM_H - 1);
        int cb = min(max(ib, 0), NUM_H - 1);

        sm->pos[tid][0] = ct * NUM_W + cl;
        sm->pos[tid][1] = ct * NUM_W + cr;
        sm->pos[tid][2] = cb * NUM_W + cr;
        sm->pos[tid][3] = cb * NUM_W + cl;

        sm->wgt[tid][0] = (vt && vl) ? wlt : 0.0f;
        sm->wgt[tid][1] = (vt && vr) ? wrt : 0.0f;
        sm->wgt[tid][2] = (vb && vr) ? wrb : 0.0f;
        sm->wgt[tid][3] = (vb && vl) ? wlb : 0.0f;
    }
    __syncthreads();

    const int wid  = tid >> 5;
    const int lane = tid & 31;

    // base: xT[b][.][.][half*128 + lane*4]  (fp16)
    const __half* base = xT_buf + ((size_t)b * HW * NUM_C)
                       + half * C_HALF + lane * 4;

    for (int bin = wid; bin < NBIN; bin += 8) {
        float4 acc = make_float4(0.f, 0.f, 0.f, 0.f);
        #pragma unroll
        for (int k = 0; k < 4; ++k) {
            float wgt = sm->wgt[bin][k];        // warp-uniform
            if (wgt != 0.0f) {
                uint2 pak = *reinterpret_cast<const uint2*>(
                    base + (size_t)sm->pos[bin][k] * NUM_C);
                float2 f0 = __half22float2(*reinterpret_cast<__half2*>(&pak.x));
                float2 f1 = __half22float2(*reinterpret_cast<__half2*>(&pak.y));
                acc.x += f0.x * wgt;
                acc.y += f0.y * wgt;
                acc.z += f1.x * wgt;
                acc.w += f1.y * wgt;
            }
        }
        sm->sout[bin][lane * 4 + 0] = fmaxf(acc.x, 0.0f);
        sm->sout[bin][lane * 4 + 1] = fmaxf(acc.y, 0.0f);
        sm->sout[bin][lane * 4 + 2] = fmaxf(acc.z, 0.0f);
        sm->sout[bin][lane * 4 + 3] = fmaxf(acc.w, 0.0f);
    }
    __syncthreads();

    float* ob = out + (size_t)roi * (NUM_C * NBIN) + (size_t)half * C_HALF * NBIN;
    for (int i = tid; i < C_HALF * NBIN; i += 256) {
        int c   = i / NBIN;
        int bin = i - c * NBIN;
        ob[i] = sm->sout[bin][c];
    }
}

// ---------------------------------------------------------------------------
// Kernels
// ---------------------------------------------------------------------------
__global__ __launch_bounds__(256) void k_t0(const float* __restrict__ x)
{
    __shared__ __align__(16) char smem[sizeof(float) * 4 * 32 * 33];
    transpose_tile(x, 0, blockIdx.x, threadIdx.x, smem);
}

// Fused: T1 (4096 tiles) + P0 (1024 pool blocks), interleaved 4:1.
// group g = i/5, r = i%5.  r==2 -> pool block g;  else transpose t = g*4 + (r<2?r:r-1)
__global__ __launch_bounds__(256) void k_fused(const float* __restrict__ x,
                                               const float* __restrict__ boxes,
                                               float* __restrict__ out)
{
    __shared__ __align__(16) char smem[sizeof(PoolSmem)];
    const int g = blockIdx.x / 5;
    const int r = blockIdx.x - g * 5;
    if (r == 2) {
        pool_block(boxes, out, 0, g, threadIdx.x, smem);
    } else {
        int t = g * 4 + (r < 2 ? r : r - 1);
        transpose_tile(x, 1, t, threadIdx.x, smem);
    }
}

__global__ __launch_bounds__(256) void k_p1(const float* __restrict__ boxes,
                                            float* __restrict__ out)
{
    __shared__ __align__(16) char smem[sizeof(PoolSmem)];
    pool_block(boxes, out, 1, blockIdx.x, threadIdx.x, smem);
}

extern "C" void kernel_launch(void* const* d_in, const int* in_sizes, int n_in,
                              void* d_out, int out_size) {
    const float* x     = (const float*)d_in[0];   // (2,256,256,256) f32
    const float* boxes = (const float*)d_in[1];   // (2,512,5) f32
    float* out = (float*)d_out;                   // (1024,256,7,7) f32
    (void)in_sizes; (void)n_in; (void)out_size;

    k_t0<<<T_PER_BATCH, 256>>>(x);                              // T0
    k_fused<<<T_PER_BATCH + P_PER_BATCH, 256>>>(x, boxes, out); // T1 ∥ P0
    k_p1<<<P_PER_BATCH, 256>>>(boxes, out);                     // P1
}